// round 5
// baseline (speedup 1.0000x reference)
#include <cuda_runtime.h>
#include <cooperative_groups.h>
#include <cstdint>

namespace cg = cooperative_groups;

#define Bb 128
#define Tt 1024
#define Dd 256
#define Hh 256
#define Gg 1024  // 4H

// 512 MB scratch for xg = x @ Wi  (static __device__ array: allowed)
__device__ float g_xg[(size_t)Bb * Tt * Gg];

// ---------------------------------------------------------------------------
// Kernel A: xg[m, g] = sum_d x[m, d] * Wi[d, g]   (M=131072, N=1024, K=256)
// Classic SGEMM: BM=BN=128, BK=16, 8x8 microtile, 256 threads.
// ---------------------------------------------------------------------------
__global__ __launch_bounds__(256) void xg_gemm(const float* __restrict__ X,
                                               const float* __restrict__ Wi) {
  __shared__ float As[16][132];  // +4 pad kills transpose-store conflicts
  __shared__ float Bs[16][128];

  const int tid = threadIdx.x;
  const size_t mbase = (size_t)blockIdx.y * 128;
  const int nbase = blockIdx.x * 128;
  const float* A0 = X + mbase * Dd;
  const float* B0 = Wi + nbase;

  const int arow = tid >> 2;          // 0..63
  const int acol = (tid & 3) << 2;    // 0,4,8,12
  const int brow = tid >> 5;          // 0..7
  const int bcol = (tid & 31) << 2;   // 0..124
  const int tx = tid & 15;
  const int ty = tid >> 4;

  float acc[8][8];
#pragma unroll
  for (int i = 0; i < 8; i++)
#pragma unroll
    for (int j = 0; j < 8; j++) acc[i][j] = 0.f;

  for (int k0 = 0; k0 < Dd; k0 += 16) {
#pragma unroll
    for (int i = 0; i < 2; i++) {
      float4 a = *(const float4*)(A0 + (size_t)(arow + i * 64) * Dd + k0 + acol);
      As[acol + 0][arow + i * 64] = a.x;
      As[acol + 1][arow + i * 64] = a.y;
      As[acol + 2][arow + i * 64] = a.z;
      As[acol + 3][arow + i * 64] = a.w;
    }
#pragma unroll
    for (int i = 0; i < 2; i++) {
      *(float4*)&Bs[brow + i * 8][bcol] =
          *(const float4*)(B0 + (size_t)(k0 + brow + i * 8) * Gg + bcol);
    }
    __syncthreads();
#pragma unroll
    for (int k = 0; k < 16; k++) {
      float ra[8], rb[8];
      *(float4*)&ra[0] = *(const float4*)&As[k][ty * 8];
      *(float4*)&ra[4] = *(const float4*)&As[k][ty * 8 + 4];
      *(float4*)&rb[0] = *(const float4*)&Bs[k][tx * 8];
      *(float4*)&rb[4] = *(const float4*)&Bs[k][tx * 8 + 4];
#pragma unroll
      for (int i = 0; i < 8; i++)
#pragma unroll
        for (int j = 0; j < 8; j++) acc[i][j] += ra[i] * rb[j];
    }
    __syncthreads();
  }

  float* C = g_xg + (mbase + (size_t)ty * 8) * Gg + nbase + tx * 8;
#pragma unroll
  for (int i = 0; i < 8; i++) {
    *(float4*)(C + (size_t)i * Gg) =
        make_float4(acc[i][0], acc[i][1], acc[i][2], acc[i][3]);
    *(float4*)(C + (size_t)i * Gg + 4) =
        make_float4(acc[i][4], acc[i][5], acc[i][6], acc[i][7]);
  }
}

// ---------------------------------------------------------------------------
// Kernel B: persistent cluster LSTM recurrence.
//   16 clusters x 8 CTAs (128 SMs), 128 threads/CTA.
//   Cluster c owns batches [8c, 8c+8). CTA rank r owns, for each gate,
//   cols [g*256 + r*32, g*256 + r*32 + 32)  -> 128 local gate columns.
//   Wh slice (128KB) SMEM-resident for all 1024 steps; h replicated per CTA,
//   ping-pong buffers, DSMEM scatter + one cluster.sync per step.
// ---------------------------------------------------------------------------

// SMEM layout (floats)
#define WHS_OFF 0        // [64 kchunks][128 cols][4]      = 32768
#define HB_OFF 32768     // [2][8 batch][256 k]            =  4096
#define GATE_OFF 36864   // [8 batch][128 cols]            =  1024
#define XGS_OFF 37888    // [2][8 batch][128 cols]         =  2048
#define BIAS_OFF 39936   // [128]                          =   128
#define SMEM_FLOATS 40064
#define SMEM_BYTES (SMEM_FLOATS * 4)

__device__ __forceinline__ float sigmoidf_(float x) {
  return 1.f / (1.f + __expf(-x));
}

__device__ __forceinline__ void prefetch_xg(float* dst, int cl, int r, int t,
                                            int tid) {
#pragma unroll
  for (int kk = 0; kk < 2; kk++) {
    int o = tid + (kk << 7);  // 0..255 : 8 batches x 32 x 16B chunks
    int b = o >> 5;
    int rem = o & 31;
    int g = rem >> 3;
    int sub = rem & 7;
    size_t srcoff = ((((size_t)(cl * 8 + b)) * Tt + t) << 10) + (g << 8) +
                    (r << 5) + (sub << 2);
    unsigned saddr =
        (unsigned)__cvta_generic_to_shared(dst + (b << 7) + (g << 5) + (sub << 2));
    asm volatile("cp.async.cg.shared.global [%0], [%1], 16;\n" ::"r"(saddr),
                 "l"(g_xg + srcoff));
  }
}

__global__ __launch_bounds__(128, 1) __cluster_dims__(8, 1, 1)
void lstm_rec(const float* __restrict__ Wh, const float* __restrict__ bh,
              float* __restrict__ out) {
  extern __shared__ float sm[];
  float* whs = sm + WHS_OFF;
  float* hb = sm + HB_OFF;
  float* gates = sm + GATE_OFF;
  float* xgs = sm + XGS_OFF;
  float* bias = sm + BIAS_OFF;

  cg::cluster_group cluster = cg::this_cluster();
  const int r = blockIdx.x;   // cluster rank 0..7
  const int cl = blockIdx.y;  // cluster id 0..15
  const int tid = threadIdx.x;

  // ---- one-time init: Wh slice (layout [k/4][col][4]), bias, h0 = 0 ----
  for (int idx = tid; idx < 32768; idx += 128) {
    int c = idx & 127;
    int k = idx >> 7;
    int gcol = ((c >> 5) << 8) + (r << 5) + (c & 31);
    whs[((k >> 2) << 9) + (c << 2) + (k & 3)] = Wh[k * Gg + gcol];
  }
  {
    int c = tid;  // 128 threads == 128 cols
    int gcol = ((c >> 5) << 8) + (r << 5) + (c & 31);
    bias[c] = bh[gcol];
  }
  for (int idx = tid; idx < 2048; idx += 128) hb[idx] = 0.f;

  prefetch_xg(xgs, cl, r, 0, tid);
  asm volatile("cp.async.commit_group;" ::: "memory");

  cluster.sync();  // smem init visible cluster-wide before remote writes

  const int ty = tid >> 6;  // 0..1  (batch quad)
  const int tx = tid & 63;  // column
  const int b0 = ty << 2;
  const int jj = tid & 31;  // update-phase col within gate
  const int bq = tid >> 5;  // 0..3 -> batches 2bq, 2bq+1
  float creg0 = 0.f, creg1 = 0.f;
  int p = 0;

  const size_t OUT_FIN = (size_t)Bb * Tt * Hh;  // 33554432

  for (int t = 0; t < Tt; t++) {
    if (t + 1 < Tt) prefetch_xg(xgs + ((t + 1) & 1) * 1024, cl, r, t + 1, tid);
    asm volatile("cp.async.commit_group;" ::: "memory");

    // ---- GEMM: gates_acc = h_prev @ Wh_slice ----
    const float4* h4 = (const float4*)(hb + p * 2048);  // [8][64]
    const float4* w4 = (const float4*)whs;              // [64][128]
    float a00 = 0.f, a01 = 0.f, a10 = 0.f, a11 = 0.f;
    float a20 = 0.f, a21 = 0.f, a30 = 0.f, a31 = 0.f;
#pragma unroll 8
    for (int kc = 0; kc < 64; kc++) {
      float4 w0 = w4[(kc << 7) + tx];
      float4 w1 = w4[(kc << 7) + tx + 64];
      float4 h0v = h4[((b0 + 0) << 6) + kc];
      float4 h1v = h4[((b0 + 1) << 6) + kc];
      float4 h2v = h4[((b0 + 2) << 6) + kc];
      float4 h3v = h4[((b0 + 3) << 6) + kc];
      a00 += h0v.x * w0.x; a00 += h0v.y * w0.y; a00 += h0v.z * w0.z; a00 += h0v.w * w0.w;
      a01 += h0v.x * w1.x; a01 += h0v.y * w1.y; a01 += h0v.z * w1.z; a01 += h0v.w * w1.w;
      a10 += h1v.x * w0.x; a10 += h1v.y * w0.y; a10 += h1v.z * w0.z; a10 += h1v.w * w0.w;
      a11 += h1v.x * w1.x; a11 += h1v.y * w1.y; a11 += h1v.z * w1.z; a11 += h1v.w * w1.w;
      a20 += h2v.x * w0.x; a20 += h2v.y * w0.y; a20 += h2v.z * w0.z; a20 += h2v.w * w0.w;
      a21 += h2v.x * w1.x; a21 += h2v.y * w1.y; a21 += h2v.z * w1.z; a21 += h2v.w * w1.w;
      a30 += h3v.x * w0.x; a30 += h3v.y * w0.y; a30 += h3v.z * w0.z; a30 += h3v.w * w0.w;
      a31 += h3v.x * w1.x; a31 += h3v.y * w1.y; a31 += h3v.z * w1.z; a31 += h3v.w * w1.w;
    }

    // xg for step t was prefetched one iter ago; make it visible to all threads
    asm volatile("cp.async.wait_group 1;" ::: "memory");
    __syncthreads();

    // ---- epilogue: add xg + bias, stage gates in smem ----
    {
      const float* xc = xgs + (t & 1) * 1024;
      float bl = bias[tx], bh_ = bias[tx + 64];
      gates[((b0 + 0) << 7) + tx]      = a00 + xc[((b0 + 0) << 7) + tx] + bl;
      gates[((b0 + 0) << 7) + tx + 64] = a01 + xc[((b0 + 0) << 7) + tx + 64] + bh_;
      gates[((b0 + 1) << 7) + tx]      = a10 + xc[((b0 + 1) << 7) + tx] + bl;
      gates[((b0 + 1) << 7) + tx + 64] = a11 + xc[((b0 + 1) << 7) + tx + 64] + bh_;
      gates[((b0 + 2) << 7) + tx]      = a20 + xc[((b0 + 2) << 7) + tx] + bl;
      gates[((b0 + 2) << 7) + tx + 64] = a21 + xc[((b0 + 2) << 7) + tx + 64] + bh_;
      gates[((b0 + 3) << 7) + tx]      = a30 + xc[((b0 + 3) << 7) + tx] + bl;
      gates[((b0 + 3) << 7) + tx + 64] = a31 + xc[((b0 + 3) << 7) + tx + 64] + bh_;
    }
    __syncthreads();

    // ---- pointwise LSTM update: this CTA owns h cols [r*32, r*32+32) ----
    float* hnext = hb + (p ^ 1) * 2048;
    const int m = (r << 5) + jj;
#pragma unroll
    for (int u = 0; u < 2; u++) {
      int b = (bq << 1) + u;
      float gi = gates[(b << 7) + jj];
      float gf = gates[(b << 7) + 32 + jj];
      float gg = gates[(b << 7) + 64 + jj];
      float go = gates[(b << 7) + 96 + jj];
      float iv = sigmoidf_(gi);
      float fv = sigmoidf_(gf);
      float gv = tanhf(gg);
      float ov = sigmoidf_(go);
      float cprev = u ? creg1 : creg0;
      float cnew = fv * cprev + iv * gv;
      if (u) creg1 = cnew; else creg0 = cnew;
      float hv = ov * tanhf(cnew);

      size_t gb = (size_t)(cl << 3) + b;
      out[((gb << 10) + t) * Hh + m] = hv;
      if (t == Tt - 1) {
        out[OUT_FIN + gb * Hh + m] = cnew;                     // c_fin
        out[OUT_FIN + (size_t)Bb * Hh + gb * Hh + m] = hv;     // h_fin
      }

      float* dst = hnext + (b << 8) + m;
#pragma unroll
      for (int rk = 0; rk < 8; rk++) {
        float* rp = cluster.map_shared_rank(dst, rk);
        *rp = hv;
      }
    }

    cluster.sync();  // h_next visible cluster-wide; prev-buffer reads done
    p ^= 1;
  }
}

// ---------------------------------------------------------------------------
extern "C" void kernel_launch(void* const* d_in, const int* in_sizes, int n_in,
                              void* d_out, int out_size) {
  const float* x = (const float*)d_in[0];    // [B, T, D]
  const float* Wi = (const float*)d_in[1];   // [D, 4H]
  const float* Wh = (const float*)d_in[2];   // [H, 4H]
  const float* bh = (const float*)d_in[3];   // [4H]
  float* out = (float*)d_out;                // outputs | c_fin | h_fin

  // Kernel A: xg = x @ Wi
  dim3 gA(Gg / 128, (Bb * Tt) / 128);  // (8, 1024)
  xg_gemm<<<gA, 256>>>(x, Wi);

  // Kernel B: persistent cluster recurrence
  cudaFuncSetAttribute(lstm_rec, cudaFuncAttributeMaxDynamicSharedMemorySize,
                       SMEM_BYTES);
  lstm_rec<<<dim3(8, 16), 128, SMEM_BYTES>>>(Wh, bh, out);
}

// round 6
// speedup vs baseline: 1.1546x; 1.1546x over previous
#include <cuda_runtime.h>
#include <cooperative_groups.h>
#include <cstdint>

namespace cg = cooperative_groups;

#define Bb 128
#define Tt 1024
#define Dd 256
#define Hh 256
#define Gg 1024  // 4H

typedef unsigned long long ull;

// 512 MB scratch for xg = x @ Wi
__device__ float g_xg[(size_t)Bb * Tt * Gg];

// ---- packed fp32x2 helpers (SASS FFMA2 — only reachable via PTX) ----
#define FMA2(d, a, b) \
  asm("fma.rn.f32x2 %0, %1, %2, %0;" : "+l"(d) : "l"(a), "l"(b))

__device__ __forceinline__ ull pack_dup(float x) {
  ull d;
  unsigned u = __float_as_uint(x);
  asm("mov.b64 %0, {%1, %1};" : "=l"(d) : "r"(u));
  return d;
}
__device__ __forceinline__ float2 unpack2(ull v) {
  float2 r;
  asm("mov.b64 {%0, %1}, %2;" : "=f"(r.x), "=f"(r.y) : "l"(v));
  return r;
}

// ---------------------------------------------------------------------------
// Kernel A: xg[m, g] = sum_d x[m, d] * Wi[d, g]   (M=131072, N=1024, K=256)
// BM=BN=128, BK=16, 8x8 microtile, 256 threads, FFMA2 inner product.
// acc[i][jp] is an f32x2 over output-column pairs; ra is dup-packed.
// ---------------------------------------------------------------------------
__global__ __launch_bounds__(256, 2) void xg_gemm(const float* __restrict__ X,
                                                  const float* __restrict__ Wi) {
  __shared__ float As[16][132];
  __shared__ float Bs[16][128];

  const int tid = threadIdx.x;
  const size_t mbase = (size_t)blockIdx.y * 128;
  const int nbase = blockIdx.x * 128;
  const float* A0 = X + mbase * Dd;
  const float* B0 = Wi + nbase;

  const int arow = tid >> 2;
  const int acol = (tid & 3) << 2;
  const int brow = tid >> 5;
  const int bcol = (tid & 31) << 2;
  const int tx = tid & 15;
  const int ty = tid >> 4;

  ull acc[8][4];
#pragma unroll
  for (int i = 0; i < 8; i++)
#pragma unroll
    for (int j = 0; j < 4; j++) acc[i][j] = 0ull;

  for (int k0 = 0; k0 < Dd; k0 += 16) {
#pragma unroll
    for (int i = 0; i < 2; i++) {
      float4 a = *(const float4*)(A0 + (size_t)(arow + i * 64) * Dd + k0 + acol);
      As[acol + 0][arow + i * 64] = a.x;
      As[acol + 1][arow + i * 64] = a.y;
      As[acol + 2][arow + i * 64] = a.z;
      As[acol + 3][arow + i * 64] = a.w;
    }
#pragma unroll
    for (int i = 0; i < 2; i++) {
      *(float4*)&Bs[brow + i * 8][bcol] =
          *(const float4*)(B0 + (size_t)(k0 + brow + i * 8) * Gg + bcol);
    }
    __syncthreads();
#pragma unroll
    for (int k = 0; k < 16; k++) {
      float ra[8];
      *(float4*)&ra[0] = *(const float4*)&As[k][ty * 8];
      *(float4*)&ra[4] = *(const float4*)&As[k][ty * 8 + 4];
      ulonglong2 rb0 = *(const ulonglong2*)&Bs[k][tx * 8];
      ulonglong2 rb1 = *(const ulonglong2*)&Bs[k][tx * 8 + 4];
      ull ra2[8];
#pragma unroll
      for (int i = 0; i < 8; i++) ra2[i] = pack_dup(ra[i]);
#pragma unroll
      for (int i = 0; i < 8; i++) {
        FMA2(acc[i][0], ra2[i], rb0.x);
        FMA2(acc[i][1], ra2[i], rb0.y);
        FMA2(acc[i][2], ra2[i], rb1.x);
        FMA2(acc[i][3], ra2[i], rb1.y);
      }
    }
    __syncthreads();
  }

  float* C = g_xg + (mbase + (size_t)ty * 8) * Gg + nbase + tx * 8;
#pragma unroll
  for (int i = 0; i < 8; i++) {
    float2 p0 = unpack2(acc[i][0]);
    float2 p1 = unpack2(acc[i][1]);
    float2 p2 = unpack2(acc[i][2]);
    float2 p3 = unpack2(acc[i][3]);
    *(float4*)(C + (size_t)i * Gg) = make_float4(p0.x, p0.y, p1.x, p1.y);
    *(float4*)(C + (size_t)i * Gg + 4) = make_float4(p2.x, p2.y, p3.x, p3.y);
  }
}

// ---------------------------------------------------------------------------
// Kernel B: persistent cluster LSTM recurrence, 16 clusters x 8 CTAs,
// 256 threads/CTA. CTA r owns gate cols {g*256 + r*32 .. +32} (128 local).
// GEMM phase: thread (ks = tid>>6, cg = tid&63) computes cols {cg, cg+64}
// for all 8 batches over k in [ks*64, ks*64+64), accumulating in f32x2
// (even-k / odd-k lanes). 4-way k-split reduced through smem partials.
// Update phase: thread (b = tid>>5, j = tid&31) owns one h element; c-state
// in a register. h replicated cluster-wide via DSMEM push; split
// barrier.cluster.arrive/wait per step.
// ---------------------------------------------------------------------------

// SMEM float offsets
#define WHS_OFF 0        // [64 kchunks][128 cols][4]  = 32768  (128 KB)
#define HB_OFF 32768     // [2][8 b][256 k]            =  4096  (16 KB)
#define PART_OFF 36864   // [4 ks][8 b][128 col]       =  4096  (16 KB)
#define XGS_OFF 40960    // [2][8 b][128 col]          =  2048  (8 KB)
#define SMEM_FLOATS 43008
#define SMEM_BYTES (SMEM_FLOATS * 4)

#define CLUSTER_ARRIVE() asm volatile("barrier.cluster.arrive.aligned;" ::: "memory")
#define CLUSTER_WAIT()   asm volatile("barrier.cluster.wait.aligned;" ::: "memory")

__device__ __forceinline__ float sigf(float x) {
  return 1.f / (1.f + __expf(-x));
}
__device__ __forceinline__ float tanhf_(float x) {
  return 2.f / (1.f + __expf(-2.f * x)) - 1.f;
}

__device__ __forceinline__ void prefetch_xg(float* dst, int cl, int r, int t,
                                            int tid) {
  int b = tid >> 5;
  int rem = tid & 31;
  int g = rem >> 3;
  int sub = rem & 7;
  size_t src = ((size_t)(cl * 8 + b) * Tt + t) * Gg + (g << 8) + (r << 5) +
               (sub << 2);
  unsigned saddr =
      (unsigned)__cvta_generic_to_shared(dst + (b << 7) + (g << 5) + (sub << 2));
  asm volatile("cp.async.cg.shared.global [%0], [%1], 16;\n" ::"r"(saddr),
               "l"(g_xg + src));
}

__global__ __launch_bounds__(256, 1) __cluster_dims__(8, 1, 1)
void lstm_rec(const float* __restrict__ Wh, const float* __restrict__ bh,
              float* __restrict__ out) {
  extern __shared__ float sm[];
  float* whs = sm + WHS_OFF;
  float* hb = sm + HB_OFF;
  float* part = sm + PART_OFF;
  float* xgs = sm + XGS_OFF;

  cg::cluster_group cluster = cg::this_cluster();
  const int r = blockIdx.x;
  const int cl = blockIdx.y;
  const int tid = threadIdx.x;

  // ---- one-time init ----
  // Wh slice, layout [k/4][col][4] so (col, k..k+3) is one 16B chunk
  for (int idx = tid; idx < 32768; idx += 256) {
    int c = idx & 127;
    int k = idx >> 7;
    int gcol = ((c >> 5) << 8) + (r << 5) + (c & 31);
    whs[((k >> 2) << 9) + (c << 2) + (k & 3)] = Wh[k * Gg + gcol];
  }
  for (int idx = tid; idx < 4096; idx += 256) hb[idx] = 0.f;

  // bias into registers (update-phase mapping: b=tid>>5, j=tid&31)
  const int ub = tid >> 5;
  const int jj = tid & 31;
  float breg[4];
#pragma unroll
  for (int g = 0; g < 4; g++) breg[g] = bh[(g << 8) + (r << 5) + jj];

  prefetch_xg(xgs, cl, r, 0, tid);
  asm volatile("cp.async.commit_group;" ::: "memory");

  cluster.sync();  // init visible cluster-wide before any remote traffic

  // GEMM-phase mapping
  const int ks = tid >> 6;  // 0..3 k-split
  const int cg = tid & 63;  // col group: cols cg, cg+64
  const int kc0 = ks << 4;

  float creg = 0.f;
  int p = 0;
  const size_t OUT_FIN = (size_t)Bb * Tt * Hh;
  const int m = (r << 5) + jj;  // global h column owned in update phase
  const size_t gb = (size_t)(cl << 3) + ub;
  float* const out_ts = out + (gb << 10) * Hh + m;

  for (int t = 0; t < Tt; t++) {
    if (t) CLUSTER_WAIT();  // pairs with arrive(t-1): h ready, buffers free

    if (t + 1 < Tt) prefetch_xg(xgs + ((t + 1) & 1) * 1024, cl, r, t + 1, tid);
    asm volatile("cp.async.commit_group;" ::: "memory");

    // ---- GEMM: partial[ks] = h_prev[:, ks*64 .. +64) @ Wh_slice ----
    const ulonglong2* w2 = (const ulonglong2*)whs;            // [kc][128]
    const ulonglong2* h2 = (const ulonglong2*)(hb + p * 2048);  // [b][64]
    ull acc[8][2];
#pragma unroll
    for (int b = 0; b < 8; b++) { acc[b][0] = 0ull; acc[b][1] = 0ull; }

#pragma unroll 4
    for (int kk = 0; kk < 16; kk++) {
      int kc = kc0 + kk;
      ulonglong2 wa = w2[(kc << 7) + cg];
      ulonglong2 wb = w2[(kc << 7) + cg + 64];
#pragma unroll
      for (int b = 0; b < 8; b++) {
        ulonglong2 hv = h2[(b << 6) + kc];
        FMA2(acc[b][0], hv.x, wa.x);
        FMA2(acc[b][0], hv.y, wa.y);
        FMA2(acc[b][1], hv.x, wb.x);
        FMA2(acc[b][1], hv.y, wb.y);
      }
    }
    // horizontal add (even-k + odd-k) and stage partials
#pragma unroll
    for (int b = 0; b < 8; b++) {
      float2 s0 = unpack2(acc[b][0]);
      float2 s1 = unpack2(acc[b][1]);
      part[(ks << 10) + (b << 7) + cg] = s0.x + s0.y;
      part[(ks << 10) + (b << 7) + cg + 64] = s1.x + s1.y;
    }

    asm volatile("cp.async.wait_group 1;" ::: "memory");
    __syncthreads();

    // ---- update: one h element per thread ----
    const float* xc = xgs + (t & 1) * 1024 + (ub << 7);
    float gv4[4];
#pragma unroll
    for (int g = 0; g < 4; g++) {
      int col = (g << 5) + jj;
      float s = part[(ub << 7) + col] + part[1024 + (ub << 7) + col] +
                part[2048 + (ub << 7) + col] + part[3072 + (ub << 7) + col];
      gv4[g] = s + xc[col] + breg[g];
    }
    float iv = sigf(gv4[0]);
    float fv = sigf(gv4[1]);
    float gg = tanhf_(gv4[2]);
    float ov = sigf(gv4[3]);
    float cnew = fv * creg + iv * gg;
    creg = cnew;
    float hv = ov * tanhf_(cnew);

    // replicate h to all 8 ranks (ping-pong buffer p^1)
    {
      float* dst = hb + ((p ^ 1) * 2048) + (ub << 8) + m;
#pragma unroll
      for (int rk = 0; rk < 8; rk++) {
        *cluster.map_shared_rank(dst, rk) = hv;
      }
    }
    CLUSTER_ARRIVE();  // release: h writes visible at next step's wait

    // global stores overlap the barrier
    out_ts[(size_t)t * Hh] = hv;
    if (t == Tt - 1) {
      out[OUT_FIN + gb * Hh + m] = cnew;
      out[OUT_FIN + (size_t)Bb * Hh + gb * Hh + m] = hv;
    }
    p ^= 1;
  }

  cluster.sync();  // no CTA exits while peer DSMEM writes may be in flight
}

// ---------------------------------------------------------------------------
extern "C" void kernel_launch(void* const* d_in, const int* in_sizes, int n_in,
                              void* d_out, int out_size) {
  const float* x = (const float*)d_in[0];    // [B, T, D]
  const float* Wi = (const float*)d_in[1];   // [D, 4H]
  const float* Wh = (const float*)d_in[2];   // [H, 4H]
  const float* bh = (const float*)d_in[3];   // [4H]
  float* out = (float*)d_out;                // outputs | c_fin | h_fin

  dim3 gA(Gg / 128, (Bb * Tt) / 128);  // (8, 1024)
  xg_gemm<<<gA, 256>>>(x, Wi);

  cudaFuncSetAttribute(lstm_rec, cudaFuncAttributeMaxDynamicSharedMemorySize,
                       SMEM_BYTES);
  lstm_rec<<<dim3(8, 16), 256, SMEM_BYTES>>>(Wh, bh, out);
}